// round 2
// baseline (speedup 1.0000x reference)
#include <cuda_runtime.h>
#include <cuda_bf16.h>

// Problem constants (from reference): B=1024, N=16, T=256
#define BB 1024
#define NN 16
#define TT 256

// Deterministic reduction scratch (one partial per block == per batch b).
__device__ float g_partial[BB];

// One thread per (b, t). Lanes map to consecutive t -> every global load of a
// cov element (b,i,j,:) or pred/tgt element (b,n,:) is a fully coalesced
// 128B transaction. Only the lower triangle (incl. diag) of cov is read.
__global__ __launch_bounds__(TT, 1)
void gll_main_kernel(const float* __restrict__ pred,
                     const float* __restrict__ tgt,
                     const float* __restrict__ cov)
{
    const int b = blockIdx.x;   // 0..1023
    const int t = threadIdx.x;  // 0..255

    // ---- load diff[n] = pred - tgt (coalesced) ----
    float diff[NN];
#pragma unroll
    for (int n = 0; n < NN; n++) {
        const size_t idx = ((size_t)b * NN + n) * TT + (size_t)t;
        diff[n] = pred[idx] - tgt[idx];
    }

    // ---- load lower triangle of Sigma (coalesced per element) ----
    // A[i][j] for j<=i only; upper entries never touched -> dead after unroll.
    float A[NN][NN];
#pragma unroll
    for (int i = 0; i < NN; i++) {
#pragma unroll
        for (int j = 0; j <= i; j++) {
            const size_t idx = (((size_t)b * NN + i) * NN + j) * TT + (size_t)t;
            A[i][j] = cov[idx];
        }
    }

    // ---- in-register Cholesky: Sigma = L L^T (fully unrolled, N=16) ----
    // logdet(Sigma) = sum_j log(d_j^2) = sum_j log(s_j) where s_j is the
    // pivot before sqrt -- saves the *2 and the sqrt->log dependency.
    float invd[NN];
    float logdet = 0.0f;
#pragma unroll
    for (int j = 0; j < NN; j++) {
        float s = A[j][j];
#pragma unroll
        for (int k = 0; k < j; k++) s -= A[j][k] * A[j][k];
        logdet += __logf(s);
        const float inv = rsqrtf(s);   // 1/d_j
        invd[j] = inv;
#pragma unroll
        for (int i = j + 1; i < NN; i++) {
            float s2 = A[i][j];
#pragma unroll
            for (int k = 0; k < j; k++) s2 -= A[i][k] * A[j][k];
            A[i][j] = s2 * inv;        // L[i][j]
        }
    }

    // ---- forward solve L y = diff ; quad = ||y||^2 = diff^T Sigma^-1 diff ----
    float y[NN];
    float quad = 0.0f;
#pragma unroll
    for (int i = 0; i < NN; i++) {
        float s = diff[i];
#pragma unroll
        for (int k = 0; k < i; k++) s -= A[i][k] * y[k];
        y[i] = s * invd[i];
        quad += y[i] * y[i];
    }

    const float val = quad + logdet;

    // ---- deterministic block reduction (256 lanes) ----
    __shared__ float red[TT];
    red[t] = val;
    __syncthreads();
#pragma unroll
    for (int off = TT / 2; off > 0; off >>= 1) {
        if (t < off) red[t] += red[t + off];
        __syncthreads();
    }
    if (t == 0) g_partial[b] = red[0];
}

// Final reduce of 1024 block partials in double, then mean.
__global__ __launch_bounds__(BB, 1)
void gll_reduce_kernel(float* __restrict__ out)
{
    __shared__ double red[BB];
    const int t = threadIdx.x;
    red[t] = (double)g_partial[t];
    __syncthreads();
#pragma unroll
    for (int off = BB / 2; off > 0; off >>= 1) {
        if (t < off) red[t] += red[t + off];
        __syncthreads();
    }
    if (t == 0) out[0] = (float)(red[0] / (double)((size_t)BB * TT));
}

extern "C" void kernel_launch(void* const* d_in, const int* in_sizes, int n_in,
                              void* d_out, int out_size)
{
    const float* pred = (const float*)d_in[0];  // prediction [B,N,T]
    const float* tgt  = (const float*)d_in[1];  // target     [B,N,T]
    const float* cov  = (const float*)d_in[2];  // cov        [B,N,N,T]
    float* out = (float*)d_out;

    gll_main_kernel<<<BB, TT>>>(pred, tgt, cov);
    gll_reduce_kernel<<<1, BB>>>(out);
}

// round 3
// speedup vs baseline: 1.9013x; 1.9013x over previous
#include <cuda_runtime.h>
#include <cuda_bf16.h>

// Problem constants: B=1024, N=16, T=256
#define BB 1024
#define NN 16
#define TT 256

// Scratch for deterministic cross-block reduction.
__device__ float g_partial[BB];
__device__ unsigned int g_count = 0;   // reset by the last block each launch

// One thread per (b, t); lanes = consecutive t -> every load is a fully
// coalesced 128B transaction. Only the lower triangle of cov is read.
//
// Bordered LDL^T: factor [[Sigma, diff],[diff^T, 0]] without sqrt and WITHOUT
// storing L -- column j dies right after its trailing update, so peak register
// pressure is triangle(136) + border(16) + few temps.
__global__ __launch_bounds__(TT, 1)
void gll_fused_kernel(const float* __restrict__ pred,
                      const float* __restrict__ tgt,
                      const float* __restrict__ cov,
                      float* __restrict__ out)
{
    const int b = blockIdx.x;   // 0..1023
    const int t = threadIdx.x;  // 0..255

    // ---- border row: diff[n] = pred - tgt (coalesced) ----
    float bv[NN];
#pragma unroll
    for (int n = 0; n < NN; n++) {
        const size_t idx = ((size_t)b * NN + n) * TT + (size_t)t;
        bv[n] = pred[idx] - tgt[idx];
    }

    // ---- lower triangle of Sigma (coalesced per element) ----
    float A[NN][NN];
#pragma unroll
    for (int i = 0; i < NN; i++) {
#pragma unroll
        for (int j = 0; j <= i; j++) {
            const size_t idx = (((size_t)b * NN + i) * NN + j) * TT + (size_t)t;
            A[i][j] = cov[idx];
        }
    }

    // ---- right-looking bordered LDL^T, discarding columns ----
    // pivot product -> single log; border elimination accumulates the
    // quadratic form  quad = diff^T Sigma^{-1} diff  as the (negated) corner
    // Schur complement.
    float prod = 1.0f;
    float quad = 0.0f;
#pragma unroll
    for (int j = 0; j < NN; j++) {
        const float d = A[j][j];
        prod *= d;
        const float r = __fdividef(1.0f, d);   // MUFU.RCP, ~2 ulp: plenty

        // border elimination (this IS the forward solve + quad accumulation)
        const float tb = bv[j] * r;
        quad += bv[j] * tb;
#pragma unroll
        for (int k = j + 1; k < NN; k++) bv[k] -= A[k][j] * tb;

        // symmetric trailing update: A[i][k] -= A[i][j] * A[k][j] / d
#pragma unroll
        for (int k = j + 1; k < NN; k++) {
            const float w = A[k][j] * r;
#pragma unroll
            for (int i = k; i < NN; i++) A[i][k] -= A[i][j] * w;
        }
        // column j of A is now dead -> registers recycled
    }

    const float val = quad + __logf(prod);

    // ---- deterministic in-block reduction over t ----
    __shared__ float red[TT];
    red[t] = val;
    __syncthreads();
#pragma unroll
    for (int off = TT / 2; off > 0; off >>= 1) {
        if (t < off) red[t] += red[t + off];
        __syncthreads();
    }

    // ---- last-block final reduction (deterministic order, double) ----
    __shared__ bool s_last;
    if (t == 0) {
        g_partial[b] = red[0];
        __threadfence();
        const unsigned v = atomicAdd(&g_count, 1u);
        s_last = (v == BB - 1u);
    }
    __syncthreads();

    if (s_last) {
        __shared__ double dred[TT];
        // fixed index order -> bitwise deterministic across replays
        double s = (double)g_partial[t]
                 + (double)g_partial[t + 256]
                 + (double)g_partial[t + 512]
                 + (double)g_partial[t + 768];
        dred[t] = s;
        __syncthreads();
#pragma unroll
        for (int off = TT / 2; off > 0; off >>= 1) {
            if (t < off) dred[t] += dred[t + off];
            __syncthreads();
        }
        if (t == 0) {
            out[0] = (float)(dred[0] / (double)((size_t)BB * TT));
            g_count = 0;   // reset for the next graph replay
        }
    }
}

extern "C" void kernel_launch(void* const* d_in, const int* in_sizes, int n_in,
                              void* d_out, int out_size)
{
    const float* pred = (const float*)d_in[0];  // prediction [B,N,T]
    const float* tgt  = (const float*)d_in[1];  // target     [B,N,T]
    const float* cov  = (const float*)d_in[2];  // cov        [B,N,N,T]
    float* out = (float*)d_out;

    gll_fused_kernel<<<BB, TT>>>(pred, tgt, cov, out);
}